// round 7
// baseline (speedup 1.0000x reference)
#include <cuda_runtime.h>

// Problem constants
#define NN   4096
#define EE   131072
#define ETOT (EE + NN)

// ---------------- device scratch (no allocs allowed) ----------------
__device__ int   d_f64;
__device__ int   d_wp[NN];
__device__ int   d_rp[NN + 1];
__device__ int   d_esrc[ETOT];

__device__ float d_xl[NN * 512];
__device__ float d_h[NN * 512];
__device__ float d_res[NN * 512];
__device__ float d_gat[NN * 512];
__device__ float d_als[NN * 4];
__device__ float d_ald[NN * 4];
__device__ float d_h2[NN * 256];
__device__ float d_Q[NN * 256];
__device__ float d_Kb[NN * 256];
__device__ float d_Vb[NN * 256];
__device__ float d_att[NN * 256];

// materialized attention scores / probabilities: [8 heads][4096 q][4096 k]
__device__ float d_S[8L * NN * NN];

// ---------------- fused single-block CSR builder ----------------
__global__ void __launch_bounds__(1024) k_csr_build(const void* ei) {
    __shared__ int scnt[NN];
    __shared__ int sh[1024];
    __shared__ int sf64;
    int t = threadIdx.x;

    if (t == 0) {
        const unsigned* u = (const unsigned*)ei;
        int f = 1;
        for (int i = 1; i < 128; i += 2)
            if (u[i] != 0u) { f = 0; break; }
        sf64 = f;
        d_f64 = f;
    }
    for (int i = t; i < NN; i += 1024) scnt[i] = 0;
    __syncthreads();
    int f64 = sf64;

    for (int e = t; e < ETOT; e += 1024) {
        int d = (e < EE)
              ? (f64 ? (int)((const long long*)ei)[(long long)EE + e]
                     : ((const int*)ei)[EE + e])
              : (e - EE);
        atomicAdd(&scnt[d], 1);
    }
    __syncthreads();

    int v[4];
    int tot = 0;
#pragma unroll
    for (int i = 0; i < 4; i++) { v[i] = scnt[t * 4 + i]; tot += v[i]; }
    sh[t] = tot;
    __syncthreads();
    for (int off = 1; off < 1024; off <<= 1) {
        int x = (t >= off) ? sh[t - off] : 0;
        __syncthreads();
        sh[t] += x;
        __syncthreads();
    }
    int run = sh[t] - tot;
#pragma unroll
    for (int i = 0; i < 4; i++) {
        d_rp[t * 4 + i] = run;
        d_wp[t * 4 + i] = run;
        run += v[i];
    }
    if (t == 1023) d_rp[NN] = run;
    __syncthreads();

    for (int e = t; e < ETOT; e += 1024) {
        int s, d;
        if (e < EE) {
            if (f64) {
                s = (int)((const long long*)ei)[e];
                d = (int)((const long long*)ei)[(long long)EE + e];
            } else {
                s = ((const int*)ei)[e];
                d = ((const int*)ei)[EE + e];
            }
        } else {
            s = d = e - EE;
        }
        int pos = atomicAdd(&d_wp[d], 1);
        d_esrc[pos] = s;
    }
}

// ---------------- fp32 GEMM: C[M,Nc] = A[M,K] @ B[K,Nc] (+bias) ----
__global__ void k_gemm(const float* __restrict__ A, const float* __restrict__ B,
                       const float* __restrict__ bias, float* __restrict__ C,
                       int M, int K, int Nc) {
    __shared__ float As[64][17];
    __shared__ float Bs[16][64];
    int tx = threadIdx.x, ty = threadIdx.y;       // 16 x 16
    int t = ty * 16 + tx;
    int rowBase = blockIdx.y * 64;
    int colBase = blockIdx.x * 64;
    float acc[4][4];
#pragma unroll
    for (int i = 0; i < 4; i++)
#pragma unroll
        for (int j = 0; j < 4; j++) acc[i][j] = 0.f;

    for (int k0 = 0; k0 < K; k0 += 16) {
#pragma unroll
        for (int i = 0; i < 4; i++) {
            int li = t * 4 + i;
            int r = li >> 4, c = li & 15;
            As[r][c] = A[(long)(rowBase + r) * K + k0 + c];
        }
#pragma unroll
        for (int i = 0; i < 4; i++) {
            int li = t * 4 + i;
            int r = li >> 6, c = li & 63;
            Bs[r][c] = B[(long)(k0 + r) * Nc + colBase + c];
        }
        __syncthreads();
#pragma unroll
        for (int kk = 0; kk < 16; kk++) {
            float a[4], b[4];
#pragma unroll
            for (int i = 0; i < 4; i++) a[i] = As[ty * 4 + i][kk];
#pragma unroll
            for (int j = 0; j < 4; j++) b[j] = Bs[kk][tx * 4 + j];
#pragma unroll
            for (int i = 0; i < 4; i++)
#pragma unroll
                for (int j = 0; j < 4; j++) acc[i][j] += a[i] * b[j];
        }
        __syncthreads();
    }
#pragma unroll
    for (int i = 0; i < 4; i++) {
        int row = rowBase + ty * 4 + i;
#pragma unroll
        for (int j = 0; j < 4; j++) {
            int col = colBase + tx * 4 + j;
            float v = acc[i][j];
            if (bias) v += bias[col];
            C[(long)row * Nc + col] = v;
        }
    }
}

// fused QKV projection: blockIdx.z selects (B, bias, C); K=Nc=256
__global__ void k_gemm_qkv(const float* __restrict__ A,
                           const float* __restrict__ B0, const float* __restrict__ b0,
                           const float* __restrict__ B1, const float* __restrict__ b1,
                           const float* __restrict__ B2, const float* __restrict__ b2,
                           float* __restrict__ C0, float* __restrict__ C1,
                           float* __restrict__ C2) {
    const float* B = (blockIdx.z == 0) ? B0 : (blockIdx.z == 1) ? B1 : B2;
    const float* bi = (blockIdx.z == 0) ? b0 : (blockIdx.z == 1) ? b1 : b2;
    float* C = (blockIdx.z == 0) ? C0 : (blockIdx.z == 1) ? C1 : C2;
    const int K = 256, Nc = 256;

    __shared__ float As[64][17];
    __shared__ float Bs[16][64];
    int tx = threadIdx.x, ty = threadIdx.y;
    int t = ty * 16 + tx;
    int rowBase = blockIdx.y * 64;
    int colBase = blockIdx.x * 64;
    float acc[4][4];
#pragma unroll
    for (int i = 0; i < 4; i++)
#pragma unroll
        for (int j = 0; j < 4; j++) acc[i][j] = 0.f;

    for (int k0 = 0; k0 < K; k0 += 16) {
#pragma unroll
        for (int i = 0; i < 4; i++) {
            int li = t * 4 + i;
            int r = li >> 4, c = li & 15;
            As[r][c] = A[(long)(rowBase + r) * K + k0 + c];
        }
#pragma unroll
        for (int i = 0; i < 4; i++) {
            int li = t * 4 + i;
            int r = li >> 6, c = li & 63;
            Bs[r][c] = B[(long)(k0 + r) * Nc + colBase + c];
        }
        __syncthreads();
#pragma unroll
        for (int kk = 0; kk < 16; kk++) {
            float a[4], b[4];
#pragma unroll
            for (int i = 0; i < 4; i++) a[i] = As[ty * 4 + i][kk];
#pragma unroll
            for (int j = 0; j < 4; j++) b[j] = Bs[kk][tx * 4 + j];
#pragma unroll
            for (int i = 0; i < 4; i++)
#pragma unroll
                for (int j = 0; j < 4; j++) acc[i][j] += a[i] * b[j];
        }
        __syncthreads();
    }
#pragma unroll
    for (int i = 0; i < 4; i++) {
        int row = rowBase + ty * 4 + i;
#pragma unroll
        for (int j = 0; j < 4; j++) {
            int col = colBase + tx * 4 + j;
            C[(long)row * Nc + col] = acc[i][j] + bi[col];
        }
    }
}

// ---------------- per-node attention coefficients -------------------
__global__ void k_coef(const float* __restrict__ xl, const float* __restrict__ as_,
                       const float* __restrict__ ad_, int H, int C) {
    int gw = (blockIdx.x * blockDim.x + threadIdx.x) >> 5;
    int lane = threadIdx.x & 31;
    if (gw >= NN * H) return;
    int n = gw / H, h = gw - n * H;
    const float* xr = xl + (long)n * H * C + h * C;
    float s1 = 0.f, s2 = 0.f;
    for (int c = lane; c < C; c += 32) {
        float xv = xr[c];
        s1 += xv * as_[h * C + c];
        s2 += xv * ad_[h * C + c];
    }
#pragma unroll
    for (int o = 16; o; o >>= 1) {
        s1 += __shfl_down_sync(0xffffffffu, s1, o);
        s2 += __shfl_down_sync(0xffffffffu, s2, o);
    }
    if (lane == 0) { d_als[n * H + h] = s1; d_ald[n * H + h] = s2; }
}

// ---------------- GAT aggregation (two-pass) ------
template <int H, int C>
__global__ void k_aggregate(const float* __restrict__ xl,
                            const float* __restrict__ bias,
                            float* __restrict__ out) {
    constexpr int HC = H * C;
    int n = blockIdx.x;
    int t = threadIdx.x;
    int h = (t * 4) / C;
    float aldn = d_ald[n * H + h];
    int e0 = d_rp[n], e1 = d_rp[n + 1];

    float mx = -1e30f;
    for (int e = e0; e < e1; e++) {
        int s = d_esrc[e];
        float v = d_als[s * H + h] + aldn;
        v = v > 0.f ? v : 0.2f * v;
        mx = fmaxf(mx, v);
    }
    float4 acc = make_float4(0.f, 0.f, 0.f, 0.f);
    float den = 0.f;
    const float4* x4 = (const float4*)xl;
    for (int e = e0; e < e1; e++) {
        int s = d_esrc[e];
        float v = d_als[s * H + h] + aldn;
        v = v > 0.f ? v : 0.2f * v;
        float w = __expf(v - mx);
        den += w;
        float4 xv = x4[(long)s * (HC / 4) + t];
        acc.x += w * xv.x; acc.y += w * xv.y;
        acc.z += w * xv.z; acc.w += w * xv.w;
    }
    float inv = 1.f / (den + 1e-16f);
    float4 bb = ((const float4*)bias)[t];
    float4 r;
    r.x = acc.x * inv + bb.x;
    r.y = acc.y * inv + bb.y;
    r.z = acc.z * inv + bb.z;
    r.w = acc.w * inv + bb.w;
    ((float4*)out)[(long)n * (HC / 4) + t] = r;
}

// ---------------- epilogue: optional ELU, LayerNorm, optional residual
template <int D>
__global__ void k_ln(const float* __restrict__ in, const float* __restrict__ g,
                     const float* __restrict__ b, const float* __restrict__ res,
                     float* __restrict__ out, float* __restrict__ res_out, int elu) {
    constexpr int T = D / 4;
    int n = blockIdx.x, t = threadIdx.x;
    float4 v = ((const float4*)in)[(long)n * T + t];
    if (elu) {
        v.x = v.x > 0.f ? v.x : expm1f(v.x);
        v.y = v.y > 0.f ? v.y : expm1f(v.y);
        v.z = v.z > 0.f ? v.z : expm1f(v.z);
        v.w = v.w > 0.f ? v.w : expm1f(v.w);
    }
    float sum = v.x + v.y + v.z + v.w;
    float sq  = v.x * v.x + v.y * v.y + v.z * v.z + v.w * v.w;
#pragma unroll
    for (int o = 16; o; o >>= 1) {
        sum += __shfl_down_sync(0xffffffffu, sum, o);
        sq  += __shfl_down_sync(0xffffffffu, sq, o);
    }
    __shared__ float a1[T / 32], a2[T / 32];
    int lane = t & 31, w = t >> 5;
    if (lane == 0) { a1[w] = sum; a2[w] = sq; }
    __syncthreads();
    float tot = 0.f, totsq = 0.f;
#pragma unroll
    for (int i = 0; i < T / 32; i++) { tot += a1[i]; totsq += a2[i]; }
    float mu = tot / (float)D;
    float var = totsq / (float)D - mu * mu;
    float rstd = rsqrtf(var + 1e-5f);
    float4 gg = ((const float4*)g)[t];
    float4 bb = ((const float4*)b)[t];
    float4 o;
    o.x = (v.x - mu) * rstd * gg.x + bb.x;
    o.y = (v.y - mu) * rstd * gg.y + bb.y;
    o.z = (v.z - mu) * rstd * gg.z + bb.z;
    o.w = (v.w - mu) * rstd * gg.w + bb.w;
    if (res) {
        float4 rr = ((const float4*)res)[(long)n * T + t];
        o.x += rr.x; o.y += rr.y; o.z += rr.z; o.w += rr.w;
    }
    ((float4*)out)[(long)n * T + t] = o;
    if (res_out) ((float4*)res_out)[(long)n * T + t] = o;
}

// ---------------- attention stage 1: S = (Q/sqrt(dk)) @ K^T per head ----
// grid (64 k-tiles, 64 q-tiles, 8 heads), block 16x16; tile 64q x 64k, dk=32
__global__ void __launch_bounds__(256) k_sgemm(const float* __restrict__ Q,
                                               const float* __restrict__ K) {
    __shared__ float As[64][36];   // scaled Q tile [qrow][c]
    __shared__ float Bt[32][68];   // K tile transposed [c][krow]
    const float sc = 0.17677669529663687f; // 1/sqrt(32)
    int h = blockIdx.z;
    int q0 = blockIdx.y * 64, k0 = blockIdx.x * 64;
    int tx = threadIdx.x, ty = threadIdx.y;
    int t = ty * 16 + tx;

#pragma unroll
    for (int i = 0; i < 2; i++) {
        int fi = t + i * 256;
        int row = fi >> 3, c4 = fi & 7;
        float4 v = *(const float4*)&Q[(long)(q0 + row) * 256 + h * 32 + c4 * 4];
        v.x *= sc; v.y *= sc; v.z *= sc; v.w *= sc;
        *(float4*)&As[row][c4 * 4] = v;
        float4 kv = *(const float4*)&K[(long)(k0 + row) * 256 + h * 32 + c4 * 4];
        Bt[c4 * 4 + 0][row] = kv.x;
        Bt[c4 * 4 + 1][row] = kv.y;
        Bt[c4 * 4 + 2][row] = kv.z;
        Bt[c4 * 4 + 3][row] = kv.w;
    }
    __syncthreads();

    float acc[4][4];
#pragma unroll
    for (int i = 0; i < 4; i++)
#pragma unroll
        for (int j = 0; j < 4; j++) acc[i][j] = 0.f;
#pragma unroll
    for (int kk = 0; kk < 32; kk++) {
        float a[4];
#pragma unroll
        for (int i = 0; i < 4; i++) a[i] = As[ty * 4 + i][kk];
        float4 b = *(const float4*)&Bt[kk][tx * 4];
#pragma unroll
        for (int i = 0; i < 4; i++) {
            acc[i][0] += a[i] * b.x;
            acc[i][1] += a[i] * b.y;
            acc[i][2] += a[i] * b.z;
            acc[i][3] += a[i] * b.w;
        }
    }
#pragma unroll
    for (int i = 0; i < 4; i++) {
        long row = (long)h * NN + q0 + ty * 4 + i;
        *(float4*)&d_S[row * NN + k0 + tx * 4] =
            make_float4(acc[i][0], acc[i][1], acc[i][2], acc[i][3]);
    }
}

// ---------------- attention stage 2: row softmax in-place ------------
// grid 8*NN blocks (one per (h,q) row), 128 threads, 32 values/thread
__global__ void __launch_bounds__(128) k_softmax() {
    float4* row = (float4*)(d_S + (long)blockIdx.x * NN);
    int t = threadIdx.x, lane = t & 31, w = t >> 5;
    float4 v[8];
    float m = -1e30f;
#pragma unroll
    for (int i = 0; i < 8; i++) {
        v[i] = row[t + i * 128];
        m = fmaxf(m, fmaxf(fmaxf(v[i].x, v[i].y), fmaxf(v[i].z, v[i].w)));
    }
#pragma unroll
    for (int o = 16; o; o >>= 1) m = fmaxf(m, __shfl_xor_sync(0xffffffffu, m, o));
    __shared__ float sm[4], ss[4];
    if (lane == 0) sm[w] = m;
    __syncthreads();
    m = fmaxf(fmaxf(sm[0], sm[1]), fmaxf(sm[2], sm[3]));

    float sum = 0.f;
#pragma unroll
    for (int i = 0; i < 8; i++) {
        v[i].x = __expf(v[i].x - m);
        v[i].y = __expf(v[i].y - m);
        v[i].z = __expf(v[i].z - m);
        v[i].w = __expf(v[i].w - m);
        sum += (v[i].x + v[i].y) + (v[i].z + v[i].w);
    }
#pragma unroll
    for (int o = 16; o; o >>= 1) sum += __shfl_xor_sync(0xffffffffu, sum, o);
    if (lane == 0) ss[w] = sum;
    __syncthreads();
    sum = (ss[0] + ss[1]) + (ss[2] + ss[3]);
    float inv = 1.f / sum;
#pragma unroll
    for (int i = 0; i < 8; i++) {
        v[i].x *= inv; v[i].y *= inv; v[i].z *= inv; v[i].w *= inv;
        row[t + i * 128] = v[i];
    }
}

// ---------------- attention stage 3: O = P @ V per head --------------
// grid (64 q-tiles, 8 heads), block 16x16; tile 64q x 32n, K loop over 4096
__global__ void __launch_bounds__(256) k_pv(const float* __restrict__ V,
                                            float* __restrict__ O) {
    __shared__ float At[32][68];   // P tile transposed [k][qrow]
    __shared__ float Bs[32][36];   // V tile [k][n]
    int h = blockIdx.y;
    int q0 = blockIdx.x * 64;
    int tx = threadIdx.x, ty = threadIdx.y;
    int t = ty * 16 + tx;

    float acc[4][2];
#pragma unroll
    for (int i = 0; i < 4; i++) { acc[i][0] = 0.f; acc[i][1] = 0.f; }

    for (int k0 = 0; k0 < NN; k0 += 32) {
        // P tile 64x32, transposed into At
#pragma unroll
        for (int i = 0; i < 2; i++) {
            int fi = t + i * 256;
            int row = fi >> 3, c4 = fi & 7;
            float4 p = *(const float4*)&d_S[((long)h * NN + q0 + row) * NN + k0 + c4 * 4];
            At[c4 * 4 + 0][row] = p.x;
            At[c4 * 4 + 1][row] = p.y;
            At[c4 * 4 + 2][row] = p.z;
            At[c4 * 4 + 3][row] = p.w;
        }
        // V tile 32x32
        {
            int r = t >> 3, c4 = t & 7;
            *(float4*)&Bs[r][c4 * 4] =
                *(const float4*)&V[(long)(k0 + r) * 256 + h * 32 + c4 * 4];
        }
        __syncthreads();
#pragma unroll
        for (int kk = 0; kk < 32; kk++) {
            float4 a = *(const float4*)&At[kk][ty * 4];
            float2 b = *(const float2*)&Bs[kk][tx * 2];
            acc[0][0] += a.x * b.x; acc[0][1] += a.x * b.y;
            acc[1][0] += a.y * b.x; acc[1][1] += a.y * b.y;
            acc[2][0] += a.z * b.x; acc[2][1] += a.z * b.y;
            acc[3][0] += a.w * b.x; acc[3][1] += a.w * b.y;
        }
        __syncthreads();
    }
#pragma unroll
    for (int i = 0; i < 4; i++) {
        int row = q0 + ty * 4 + i;
        *(float2*)&O[(long)row * 256 + h * 32 + tx * 2] =
            make_float2(acc[i][0], acc[i][1]);
    }
}

// ---------------- launch -----------------------------------------------
extern "C" void kernel_launch(void* const* d_in, const int* in_sizes, int n_in,
                              void* d_out, int out_size) {
    const float* x   = (const float*)d_in[0];
    const void*  ei  = d_in[1];
    const float* W0  = (const float*)d_in[2];
    const float* as0 = (const float*)d_in[3];
    const float* ad0 = (const float*)d_in[4];
    const float* b0  = (const float*)d_in[5];
    const float* W1  = (const float*)d_in[6];
    const float* as1 = (const float*)d_in[7];
    const float* ad1 = (const float*)d_in[8];
    const float* b1  = (const float*)d_in[9];
    const float* W2  = (const float*)d_in[10];
    const float* as2 = (const float*)d_in[11];
    const float* ad2 = (const float*)d_in[12];
    const float* b2  = (const float*)d_in[13];
    const float* g0  = (const float*)d_in[14];
    const float* be0 = (const float*)d_in[15];
    const float* g1  = (const float*)d_in[16];
    const float* be1 = (const float*)d_in[17];
    const float* g2  = (const float*)d_in[18];
    const float* be2 = (const float*)d_in[19];
    const float* wq  = (const float*)d_in[20];
    const float* bq  = (const float*)d_in[21];
    const float* wk  = (const float*)d_in[22];
    const float* bk  = (const float*)d_in[23];
    const float* wv  = (const float*)d_in[24];
    const float* bv  = (const float*)d_in[25];
    const float* wo  = (const float*)d_in[26];
    const float* bo  = (const float*)d_in[27];
    float* out = (float*)d_out;

    dim3 tb(16, 16);

    k_csr_build<<<1, 1024>>>(ei);

    // ---- layer 0: 128 -> 4x128 ----
    k_gemm<<<dim3(512 / 64, NN / 64), tb>>>(x, W0, nullptr, d_xl, NN, 128, 512);
    k_coef<<<(NN * 4 * 32 + 255) / 256, 256>>>(d_xl, as0, ad0, 4, 128);
    k_aggregate<4, 128><<<NN, 128>>>(d_xl, b0, d_gat);
    k_ln<512><<<NN, 128>>>(d_gat, g0, be0, nullptr, d_h, d_res, 1);

    // ---- layer 1: 512 -> 4x128, residual ----
    k_gemm<<<dim3(512 / 64, NN / 64), tb>>>(d_h, W1, nullptr, d_xl, NN, 512, 512);
    k_coef<<<(NN * 4 * 32 + 255) / 256, 256>>>(d_xl, as1, ad1, 4, 128);
    k_aggregate<4, 128><<<NN, 128>>>(d_xl, b1, d_gat);
    k_ln<512><<<NN, 128>>>(d_gat, g1, be1, d_res, d_h, nullptr, 1);

    // ---- layer 2: 512 -> 1x256, no ELU ----
    k_gemm<<<dim3(256 / 64, NN / 64), tb>>>(d_h, W2, nullptr, d_xl, NN, 512, 256);
    k_coef<<<(NN * 1 * 32 + 255) / 256, 256>>>(d_xl, as2, ad2, 1, 256);
    k_aggregate<1, 256><<<NN, 64>>>(d_xl, b2, d_gat);
    k_ln<256><<<NN, 64>>>(d_gat, g2, be2, nullptr, d_h2, nullptr, 0);

    // ---- dense MHA (materialized S) ----
    k_gemm_qkv<<<dim3(256 / 64, NN / 64, 3), tb>>>(d_h2, wq, bq, wk, bk, wv, bv,
                                                   d_Q, d_Kb, d_Vb);
    k_sgemm<<<dim3(NN / 64, NN / 64, 8), tb>>>(d_Q, d_Kb);
    k_softmax<<<8 * NN, 128>>>();
    k_pv<<<dim3(NN / 64, 8), tb>>>(d_Vb, d_att);
    k_gemm<<<dim3(256 / 64, NN / 64), tb>>>(d_att, wo, bo, out, NN, 256, 256);
}

// round 8
// speedup vs baseline: 1.3134x; 1.3134x over previous
#include <cuda_runtime.h>
#include <cstdio>

// Problem constants
#define NN   4096
#define EE   131072
#define ETOT (EE + NN)

// ---------------- device scratch (no allocs allowed) ----------------
__device__ int   d_f64;
__device__ int   d_wp[NN];
__device__ int   d_rp[NN + 1];
__device__ int   d_esrc[ETOT];

__device__ float d_xl[NN * 512];
__device__ float d_h[NN * 512];
__device__ float d_res[NN * 512];
__device__ float d_gat[NN * 512];
__device__ float d_als[NN * 4];
__device__ float d_ald[NN * 4];
__device__ float d_h2[NN * 256];
__device__ float d_Q[NN * 256];
__device__ float d_Kb[NN * 256];
__device__ float d_Vb[NN * 256];
__device__ float d_att[NN * 256];

// ---------------- timestamps ----------------
__device__ unsigned long long d_ts[24];

__global__ void k_stamp(int i) {
    unsigned long long t;
    asm volatile("mov.u64 %0, %%globaltimer;" : "=l"(t));
    d_ts[i] = t;
}

__global__ void k_report() {
    // one line per replay; µs per stage
    printf("STAGES csr=%.1f gemm0=%.1f coef0=%.1f agg0=%.1f ln0=%.1f "
           "gemm1=%.1f coef1=%.1f agg1=%.1f ln1=%.1f "
           "gemm2=%.1f coef2=%.1f agg2=%.1f ln2=%.1f "
           "qkv=%.1f attn=%.1f outp=%.1f total=%.1f\n",
           (d_ts[1] - d_ts[0]) * 1e-3, (d_ts[2] - d_ts[1]) * 1e-3,
           (d_ts[3] - d_ts[2]) * 1e-3, (d_ts[4] - d_ts[3]) * 1e-3,
           (d_ts[5] - d_ts[4]) * 1e-3, (d_ts[6] - d_ts[5]) * 1e-3,
           (d_ts[7] - d_ts[6]) * 1e-3, (d_ts[8] - d_ts[7]) * 1e-3,
           (d_ts[9] - d_ts[8]) * 1e-3, (d_ts[10] - d_ts[9]) * 1e-3,
           (d_ts[11] - d_ts[10]) * 1e-3, (d_ts[12] - d_ts[11]) * 1e-3,
           (d_ts[13] - d_ts[12]) * 1e-3, (d_ts[14] - d_ts[13]) * 1e-3,
           (d_ts[15] - d_ts[14]) * 1e-3, (d_ts[16] - d_ts[15]) * 1e-3,
           (d_ts[16] - d_ts[0]) * 1e-3);
}

// ---------------- fused single-block CSR builder ----------------
__global__ void __launch_bounds__(1024) k_csr_build(const void* ei) {
    __shared__ int scnt[NN];
    __shared__ int sh[1024];
    __shared__ int sf64;
    int t = threadIdx.x;

    if (t == 0) {
        const unsigned* u = (const unsigned*)ei;
        int f = 1;
        for (int i = 1; i < 128; i += 2)
            if (u[i] != 0u) { f = 0; break; }
        sf64 = f;
        d_f64 = f;
    }
    for (int i = t; i < NN; i += 1024) scnt[i] = 0;
    __syncthreads();
    int f64 = sf64;

    for (int e = t; e < ETOT; e += 1024) {
        int d = (e < EE)
              ? (f64 ? (int)((const long long*)ei)[(long long)EE + e]
                     : ((const int*)ei)[EE + e])
              : (e - EE);
        atomicAdd(&scnt[d], 1);
    }
    __syncthreads();

    int v[4];
    int tot = 0;
#pragma unroll
    for (int i = 0; i < 4; i++) { v[i] = scnt[t * 4 + i]; tot += v[i]; }
    sh[t] = tot;
    __syncthreads();
    for (int off = 1; off < 1024; off <<= 1) {
        int x = (t >= off) ? sh[t - off] : 0;
        __syncthreads();
        sh[t] += x;
        __syncthreads();
    }
    int run = sh[t] - tot;
#pragma unroll
    for (int i = 0; i < 4; i++) {
        d_rp[t * 4 + i] = run;
        d_wp[t * 4 + i] = run;
        run += v[i];
    }
    if (t == 1023) d_rp[NN] = run;
    __syncthreads();

    for (int e = t; e < ETOT; e += 1024) {
        int s, d;
        if (e < EE) {
            if (f64) {
                s = (int)((const long long*)ei)[e];
                d = (int)((const long long*)ei)[(long long)EE + e];
            } else {
                s = ((const int*)ei)[e];
                d = ((const int*)ei)[EE + e];
            }
        } else {
            s = d = e - EE;
        }
        int pos = atomicAdd(&d_wp[d], 1);
        d_esrc[pos] = s;
    }
}

// ---------------- fp32 GEMM: C[M,Nc] = A[M,K] @ B[K,Nc] (+bias) ----
__global__ void k_gemm(const float* __restrict__ A, const float* __restrict__ B,
                       const float* __restrict__ bias, float* __restrict__ C,
                       int M, int K, int Nc) {
    __shared__ float As[64][17];
    __shared__ float Bs[16][64];
    int tx = threadIdx.x, ty = threadIdx.y;       // 16 x 16
    int t = ty * 16 + tx;
    int rowBase = blockIdx.y * 64;
    int colBase = blockIdx.x * 64;
    float acc[4][4];
#pragma unroll
    for (int i = 0; i < 4; i++)
#pragma unroll
        for (int j = 0; j < 4; j++) acc[i][j] = 0.f;

    for (int k0 = 0; k0 < K; k0 += 16) {
#pragma unroll
        for (int i = 0; i < 4; i++) {
            int li = t * 4 + i;
            int r = li >> 4, c = li & 15;
            As[r][c] = A[(long)(rowBase + r) * K + k0 + c];
        }
#pragma unroll
        for (int i = 0; i < 4; i++) {
            int li = t * 4 + i;
            int r = li >> 6, c = li & 63;
            Bs[r][c] = B[(long)(k0 + r) * Nc + colBase + c];
        }
        __syncthreads();
#pragma unroll
        for (int kk = 0; kk < 16; kk++) {
            float a[4], b[4];
#pragma unroll
            for (int i = 0; i < 4; i++) a[i] = As[ty * 4 + i][kk];
#pragma unroll
            for (int j = 0; j < 4; j++) b[j] = Bs[kk][tx * 4 + j];
#pragma unroll
            for (int i = 0; i < 4; i++)
#pragma unroll
                for (int j = 0; j < 4; j++) acc[i][j] += a[i] * b[j];
        }
        __syncthreads();
    }
#pragma unroll
    for (int i = 0; i < 4; i++) {
        int row = rowBase + ty * 4 + i;
#pragma unroll
        for (int j = 0; j < 4; j++) {
            int col = colBase + tx * 4 + j;
            float v = acc[i][j];
            if (bias) v += bias[col];
            C[(long)row * Nc + col] = v;
        }
    }
}

// fused QKV projection: blockIdx.z selects (B, bias, C); K=Nc=256
__global__ void k_gemm_qkv(const float* __restrict__ A,
                           const float* __restrict__ B0, const float* __restrict__ b0,
                           const float* __restrict__ B1, const float* __restrict__ b1,
                           const float* __restrict__ B2, const float* __restrict__ b2,
                           float* __restrict__ C0, float* __restrict__ C1,
                           float* __restrict__ C2) {
    const float* B = (blockIdx.z == 0) ? B0 : (blockIdx.z == 1) ? B1 : B2;
    const float* bi = (blockIdx.z == 0) ? b0 : (blockIdx.z == 1) ? b1 : b2;
    float* C = (blockIdx.z == 0) ? C0 : (blockIdx.z == 1) ? C1 : C2;
    const int K = 256, Nc = 256;

    __shared__ float As[64][17];
    __shared__ float Bs[16][64];
    int tx = threadIdx.x, ty = threadIdx.y;
    int t = ty * 16 + tx;
    int rowBase = blockIdx.y * 64;
    int colBase = blockIdx.x * 64;
    float acc[4][4];
#pragma unroll
    for (int i = 0; i < 4; i++)
#pragma unroll
        for (int j = 0; j < 4; j++) acc[i][j] = 0.f;

    for (int k0 = 0; k0 < K; k0 += 16) {
#pragma unroll
        for (int i = 0; i < 4; i++) {
            int li = t * 4 + i;
            int r = li >> 4, c = li & 15;
            As[r][c] = A[(long)(rowBase + r) * K + k0 + c];
        }
#pragma unroll
        for (int i = 0; i < 4; i++) {
            int li = t * 4 + i;
            int r = li >> 6, c = li & 63;
            Bs[r][c] = B[(long)(k0 + r) * Nc + colBase + c];
        }
        __syncthreads();
#pragma unroll
        for (int kk = 0; kk < 16; kk++) {
            float a[4], b[4];
#pragma unroll
            for (int i = 0; i < 4; i++) a[i] = As[ty * 4 + i][kk];
#pragma unroll
            for (int j = 0; j < 4; j++) b[j] = Bs[kk][tx * 4 + j];
#pragma unroll
            for (int i = 0; i < 4; i++)
#pragma unroll
                for (int j = 0; j < 4; j++) acc[i][j] += a[i] * b[j];
        }
        __syncthreads();
    }
#pragma unroll
    for (int i = 0; i < 4; i++) {
        int row = rowBase + ty * 4 + i;
#pragma unroll
        for (int j = 0; j < 4; j++) {
            int col = colBase + tx * 4 + j;
            C[(long)row * Nc + col] = acc[i][j] + bi[col];
        }
    }
}

// ---------------- per-node attention coefficients -------------------
__global__ void k_coef(const float* __restrict__ xl, const float* __restrict__ as_,
                       const float* __restrict__ ad_, int H, int C) {
    int gw = (blockIdx.x * blockDim.x + threadIdx.x) >> 5;
    int lane = threadIdx.x & 31;
    if (gw >= NN * H) return;
    int n = gw / H, h = gw - n * H;
    const float* xr = xl + (long)n * H * C + h * C;
    float s1 = 0.f, s2 = 0.f;
    for (int c = lane; c < C; c += 32) {
        float xv = xr[c];
        s1 += xv * as_[h * C + c];
        s2 += xv * ad_[h * C + c];
    }
#pragma unroll
    for (int o = 16; o; o >>= 1) {
        s1 += __shfl_down_sync(0xffffffffu, s1, o);
        s2 += __shfl_down_sync(0xffffffffu, s2, o);
    }
    if (lane == 0) { d_als[n * H + h] = s1; d_ald[n * H + h] = s2; }
}

// ---------------- GAT aggregation (two-pass) ------
template <int H, int C>
__global__ void k_aggregate(const float* __restrict__ xl,
                            const float* __restrict__ bias,
                            float* __restrict__ out) {
    constexpr int HC = H * C;
    int n = blockIdx.x;
    int t = threadIdx.x;
    int h = (t * 4) / C;
    float aldn = d_ald[n * H + h];
    int e0 = d_rp[n], e1 = d_rp[n + 1];

    float mx = -1e30f;
    for (int e = e0; e < e1; e++) {
        int s = d_esrc[e];
        float v = d_als[s * H + h] + aldn;
        v = v > 0.f ? v : 0.2f * v;
        mx = fmaxf(mx, v);
    }
    float4 acc = make_float4(0.f, 0.f, 0.f, 0.f);
    float den = 0.f;
    const float4* x4 = (const float4*)xl;
    for (int e = e0; e < e1; e++) {
        int s = d_esrc[e];
        float v = d_als[s * H + h] + aldn;
        v = v > 0.f ? v : 0.2f * v;
        float w = __expf(v - mx);
        den += w;
        float4 xv = x4[(long)s * (HC / 4) + t];
        acc.x += w * xv.x; acc.y += w * xv.y;
        acc.z += w * xv.z; acc.w += w * xv.w;
    }
    float inv = 1.f / (den + 1e-16f);
    float4 bb = ((const float4*)bias)[t];
    float4 r;
    r.x = acc.x * inv + bb.x;
    r.y = acc.y * inv + bb.y;
    r.z = acc.z * inv + bb.z;
    r.w = acc.w * inv + bb.w;
    ((float4*)out)[(long)n * (HC / 4) + t] = r;
}

// ---------------- epilogue: optional ELU, LayerNorm, optional residual
template <int D>
__global__ void k_ln(const float* __restrict__ in, const float* __restrict__ g,
                     const float* __restrict__ b, const float* __restrict__ res,
                     float* __restrict__ out, float* __restrict__ res_out, int elu) {
    constexpr int T = D / 4;
    int n = blockIdx.x, t = threadIdx.x;
    float4 v = ((const float4*)in)[(long)n * T + t];
    if (elu) {
        v.x = v.x > 0.f ? v.x : expm1f(v.x);
        v.y = v.y > 0.f ? v.y : expm1f(v.y);
        v.z = v.z > 0.f ? v.z : expm1f(v.z);
        v.w = v.w > 0.f ? v.w : expm1f(v.w);
    }
    float sum = v.x + v.y + v.z + v.w;
    float sq  = v.x * v.x + v.y * v.y + v.z * v.z + v.w * v.w;
#pragma unroll
    for (int o = 16; o; o >>= 1) {
        sum += __shfl_down_sync(0xffffffffu, sum, o);
        sq  += __shfl_down_sync(0xffffffffu, sq, o);
    }
    __shared__ float a1[T / 32], a2[T / 32];
    int lane = t & 31, w = t >> 5;
    if (lane == 0) { a1[w] = sum; a2[w] = sq; }
    __syncthreads();
    float tot = 0.f, totsq = 0.f;
#pragma unroll
    for (int i = 0; i < T / 32; i++) { tot += a1[i]; totsq += a2[i]; }
    float mu = tot / (float)D;
    float var = totsq / (float)D - mu * mu;
    float rstd = rsqrtf(var + 1e-5f);
    float4 gg = ((const float4*)g)[t];
    float4 bb = ((const float4*)b)[t];
    float4 o;
    o.x = (v.x - mu) * rstd * gg.x + bb.x;
    o.y = (v.y - mu) * rstd * gg.y + bb.y;
    o.z = (v.z - mu) * rstd * gg.z + bb.z;
    o.w = (v.w - mu) * rstd * gg.w + bb.w;
    if (res) {
        float4 rr = ((const float4*)res)[(long)n * T + t];
        o.x += rr.x; o.y += rr.y; o.z += rr.z; o.w += rr.w;
    }
    ((float4*)out)[(long)n * T + t] = o;
    if (res_out) ((float4*)res_out)[(long)n * T + t] = o;
}

// ---------------- dense MHA: flash-style, 1 thread = 1 query ---------
__global__ void __launch_bounds__(128) k_attn(const float* __restrict__ Q,
                                              const float* __restrict__ K,
                                              const float* __restrict__ V,
                                              float* __restrict__ O) {
    int h = blockIdx.y;
    int q = blockIdx.x * 128 + threadIdx.x;
    const float sc = 0.17677669529663687f; // 1/sqrt(32)
    float qr[32];
#pragma unroll
    for (int c = 0; c < 32; c++) qr[c] = Q[(long)q * 256 + h * 32 + c] * sc;
    float m = -1e30f, l = 0.f;
    float o[32];
#pragma unroll
    for (int c = 0; c < 32; c++) o[c] = 0.f;

    __shared__ float Ks[32][32];
    __shared__ float Vs[32][32];
    int t = threadIdx.x;
    for (int k0 = 0; k0 < NN; k0 += 32) {
#pragma unroll
        for (int i = 0; i < 2; i++) {
            int li = t * 2 + i;
            int r = li >> 3, c = (li & 7) * 4;
            *(float4*)&Ks[r][c] = *(const float4*)&K[(long)(k0 + r) * 256 + h * 32 + c];
            *(float4*)&Vs[r][c] = *(const float4*)&V[(long)(k0 + r) * 256 + h * 32 + c];
        }
        __syncthreads();
        float s[32];
        float tm = m;
#pragma unroll
        for (int j = 0; j < 32; j++) {
            float a0 = 0.f, a1 = 0.f, a2 = 0.f, a3 = 0.f;
#pragma unroll
            for (int c4 = 0; c4 < 8; c4++) {
                float4 kv = *(const float4*)&Ks[j][c4 * 4];
                a0 += qr[c4 * 4 + 0] * kv.x;
                a1 += qr[c4 * 4 + 1] * kv.y;
                a2 += qr[c4 * 4 + 2] * kv.z;
                a3 += qr[c4 * 4 + 3] * kv.w;
            }
            float acc = (a0 + a1) + (a2 + a3);
            s[j] = acc;
            tm = fmaxf(tm, acc);
        }
        float corr = __expf(m - tm);
        l *= corr;
#pragma unroll
        for (int c = 0; c < 32; c++) o[c] *= corr;
#pragma unroll
        for (int j = 0; j < 32; j++) {
            float p = __expf(s[j] - tm);
            l += p;
#pragma unroll
            for (int c4 = 0; c4 < 8; c4++) {
                float4 vv = *(const float4*)&Vs[j][c4 * 4];
                o[c4 * 4 + 0] += p * vv.x;
                o[c4 * 4 + 1] += p * vv.y;
                o[c4 * 4 + 2] += p * vv.z;
                o[c4 * 4 + 3] += p * vv.w;
            }
        }
        m = tm;
        __syncthreads();
    }
    float inv = 1.f / l;
#pragma unroll
    for (int c = 0; c < 32; c++) O[(long)q * 256 + h * 32 + c] = o[c] * inv;
}

// ---------------- launch -----------------------------------------------
extern "C" void kernel_launch(void* const* d_in, const int* in_sizes, int n_in,
                              void* d_out, int out_size) {
    const float* x   = (const float*)d_in[0];
    const void*  ei  = d_in[1];
    const float* W0  = (const float*)d_in[2];
    const float* as0 = (const float*)d_in[3];
    const float* ad0 = (const float*)d_in[4];
    const float* b0  = (const float*)d_in[5];
    const float* W1  = (const float*)d_in[6];
    const float* as1 = (const float*)d_in[7];
    const float* ad1 = (const float*)d_in[8];
    const float* b1  = (const float*)d_in[9];
    const float* W2  = (const float*)d_in[10];
    const float* as2 = (const float*)d_in[11];
    const float* ad2 = (const float*)d_in[12];
    const float* b2  = (const float*)d_in[13];
    const float* g0  = (const float*)d_in[14];
    const float* be0 = (const float*)d_in[15];
    const float* g1  = (const float*)d_in[16];
    const float* be1 = (const float*)d_in[17];
    const float* g2  = (const float*)d_in[18];
    const float* be2 = (const float*)d_in[19];
    const float* wq  = (const float*)d_in[20];
    const float* bq  = (const float*)d_in[21];
    const float* wk  = (const float*)d_in[22];
    const float* bk  = (const float*)d_in[23];
    const float* wv  = (const float*)d_in[24];
    const float* bv  = (const float*)d_in[25];
    const float* wo  = (const float*)d_in[26];
    const float* bo  = (const float*)d_in[27];
    float* out = (float*)d_out;

    dim3 tb(16, 16);

    k_stamp<<<1, 1>>>(0);
    k_csr_build<<<1, 1024>>>(ei);
    k_stamp<<<1, 1>>>(1);

    // ---- layer 0: 128 -> 4x128 ----
    k_gemm<<<dim3(512 / 64, NN / 64), tb>>>(x, W0, nullptr, d_xl, NN, 128, 512);
    k_stamp<<<1, 1>>>(2);
    k_coef<<<(NN * 4 * 32 + 255) / 256, 256>>>(d_xl, as0, ad0, 4, 128);
    k_stamp<<<1, 1>>>(3);
    k_aggregate<4, 128><<<NN, 128>>>(d_xl, b0, d_gat);
    k_stamp<<<1, 1>>>(4);
    k_ln<512><<<NN, 128>>>(d_gat, g0, be0, nullptr, d_h, d_res, 1);
    k_stamp<<<1, 1>>>(5);

    // ---- layer 1: 512 -> 4x128, residual ----
    k_gemm<<<dim3(512 / 64, NN / 64), tb>>>(d_h, W1, nullptr, d_xl, NN, 512, 512);
    k_stamp<<<1, 1>>>(6);
    k_coef<<<(NN * 4 * 32 + 255) / 256, 256>>>(d_xl, as1, ad1, 4, 128);
    k_stamp<<<1, 1>>>(7);
    k_aggregate<4, 128><<<NN, 128>>>(d_xl, b1, d_gat);
    k_stamp<<<1, 1>>>(8);
    k_ln<512><<<NN, 128>>>(d_gat, g1, be1, d_res, d_h, nullptr, 1);
    k_stamp<<<1, 1>>>(9);

    // ---- layer 2: 512 -> 1x256, no ELU ----
    k_gemm<<<dim3(256 / 64, NN / 64), tb>>>(d_h, W2, nullptr, d_xl, NN, 512, 256);
    k_stamp<<<1, 1>>>(10);
    k_coef<<<(NN * 1 * 32 + 255) / 256, 256>>>(d_xl, as2, ad2, 1, 256);
    k_stamp<<<1, 1>>>(11);
    k_aggregate<1, 256><<<NN, 64>>>(d_xl, b2, d_gat);
    k_stamp<<<1, 1>>>(12);
    k_ln<256><<<NN, 64>>>(d_gat, g2, be2, nullptr, d_h2, nullptr, 0);
    k_stamp<<<1, 1>>>(13);

    // ---- dense MHA ----
    k_gemm_qkv<<<dim3(256 / 64, NN / 64, 3), tb>>>(d_h2, wq, bq, wk, bk, wv, bv,
                                                   d_Q, d_Kb, d_Vb);
    k_stamp<<<1, 1>>>(14);
    k_attn<<<dim3(NN / 128, 8), 128>>>(d_Q, d_Kb, d_Vb, d_att);
    k_stamp<<<1, 1>>>(15);
    k_gemm<<<dim3(256 / 64, NN / 64), tb>>>(d_att, wo, bo, out, NN, 256, 256);
    k_stamp<<<1, 1>>>(16);

    k_report<<<1, 1>>>();
}